// round 6
// baseline (speedup 1.0000x reference)
#include <cuda_runtime.h>
#include <cuda_bf16.h>
#include <cstdint>

#define T_TOK 2048
#define H_DIM 2048
#define I_DIM 5632
#define N_EXP 8
#define MAXT  40
#define RMAX  (MAXT * 128)
#define NCH1  (H_DIM / 32)   /* 64  */
#define NCH2  (I_DIM / 32)   /* 176 */
#define WELEM (N_EXP * I_DIM * H_DIM)      /* 92274688 per tensor */

// ---------------- scratch (device globals; allocation-free) -----------------
__device__ uint32_t d_wgh[WELEM / 2], d_wgl[WELEM / 2];
__device__ uint32_t d_wuh[WELEM / 2], d_wul[WELEM / 2];
__device__ uint32_t d_wdh[WELEM / 2], d_wdl[WELEM / 2];
__device__ uint32_t d_xh [RMAX * H_DIM / 2], d_xl [RMAX * H_DIM / 2];
__device__ uint32_t d_ah [(size_t)RMAX * I_DIM / 2], d_al [(size_t)RMAX * I_DIM / 2];
__device__ float d_ys [RMAX * H_DIM];
__device__ int   d_topi[T_TOK * 2];
__device__ float d_topw[T_TOK * 2];
__device__ int   d_cnt [N_EXP];
__device__ int   d_fill[N_EXP];
__device__ int   d_off [N_EXP];
__device__ int   d_tile_expert[MAXT];
__device__ int   d_ntiles;
__device__ float d_row_w[RMAX];
__device__ int   d_row_of[T_TOK * 2];

// ---------------- helpers ----------------------------------------------------
__device__ __forceinline__ uint32_t smem_u32(const void* p) {
    uint32_t a;
    asm("{ .reg .u64 t; cvta.to.shared.u64 t, %1; cvt.u32.u64 %0, t; }" : "=r"(a) : "l"(p));
    return a;
}

__device__ __forceinline__ void split2(float a, float b, uint32_t& h, uint32_t& l) {
    asm("cvt.rn.bf16x2.f32 %0, %1, %2;" : "=r"(h) : "f"(b), "f"(a));
    float af = __uint_as_float(h << 16);
    float bf = __uint_as_float(h & 0xffff0000u);
    asm("cvt.rn.bf16x2.f32 %0, %1, %2;" : "=r"(l) : "f"(b - bf), "f"(a - af));
}

__device__ __forceinline__ void mma16816(float* c,
    uint32_t a0, uint32_t a1, uint32_t a2, uint32_t a3, uint32_t b0, uint32_t b1) {
    asm("mma.sync.aligned.m16n8k16.row.col.f32.bf16.bf16.f32 "
        "{%0,%1,%2,%3}, {%4,%5,%6,%7}, {%8,%9}, {%0,%1,%2,%3};"
        : "+f"(c[0]), "+f"(c[1]), "+f"(c[2]), "+f"(c[3])
        : "r"(a0), "r"(a1), "r"(a2), "r"(a3), "r"(b0), "r"(b1));
}

#define LDSM4(r, a) \
    asm volatile("ldmatrix.sync.aligned.m8n8.x4.shared.b16 {%0,%1,%2,%3}, [%4];" \
        : "=r"((r)[0]), "=r"((r)[1]), "=r"((r)[2]), "=r"((r)[3]) : "r"(a))

#define CPA(dst, src) \
    asm volatile("cp.async.cg.shared.global [%0], [%1], 16;" :: "r"(dst), "l"(src))
#define CPC() asm volatile("cp.async.commit_group;" ::: "memory")
#define CPW(n) asm volatile("cp.async.wait_group %0;" :: "n"(n) : "memory")

__device__ __forceinline__ float silu(float g) { return g / (1.f + __expf(-g)); }

// ---------------- pre-split weights -----------------------------------------
__global__ void k_split(const float4* __restrict__ src, uint2* __restrict__ dh,
                        uint2* __restrict__ dl, int n4) {
    for (int i = blockIdx.x * blockDim.x + threadIdx.x; i < n4;
         i += gridDim.x * blockDim.x) {
        float4 v = src[i];
        uint32_t h0, l0, h1, l1;
        split2(v.x, v.y, h0, l0);
        split2(v.z, v.w, h1, l1);
        dh[i] = make_uint2(h0, h1);
        dl[i] = make_uint2(l0, l1);
    }
}

// ---------------- routing ----------------------------------------------------
__global__ void k_init() {
    int i = threadIdx.x;
    if (i < N_EXP) { d_cnt[i] = 0; d_fill[i] = 0; }
}

__global__ void k_router(const float* __restrict__ x, const float* __restrict__ gw) {
    int warp = threadIdx.x >> 5, lane = threadIdx.x & 31;
    int t = blockIdx.x * 8 + warp;
    const float* xr = x + (size_t)t * H_DIM;
    float acc[N_EXP];
#pragma unroll
    for (int e = 0; e < N_EXP; e++) acc[e] = 0.f;
    for (int h = lane; h < H_DIM; h += 32) {
        float xv = xr[h];
#pragma unroll
        for (int e = 0; e < N_EXP; e++) acc[e] += xv * gw[e * H_DIM + h];
    }
#pragma unroll
    for (int e = 0; e < N_EXP; e++)
#pragma unroll
        for (int o = 16; o > 0; o >>= 1) acc[e] += __shfl_xor_sync(0xffffffffu, acc[e], o);

    if (lane == 0) {
        float mx = acc[0];
#pragma unroll
        for (int e = 1; e < N_EXP; e++) mx = fmaxf(mx, acc[e]);
        float p[N_EXP], s = 0.f;
#pragma unroll
        for (int e = 0; e < N_EXP; e++) { p[e] = __expf(acc[e] - mx); s += p[e]; }
        float inv = 1.f / s;
#pragma unroll
        for (int e = 0; e < N_EXP; e++) p[e] *= inv;
        int i0 = 0;
#pragma unroll
        for (int e = 1; e < N_EXP; e++) if (p[e] > p[i0]) i0 = e;
        int i1 = (i0 == 0) ? 1 : 0;
#pragma unroll
        for (int e = 0; e < N_EXP; e++) if (e != i0 && p[e] > p[i1]) i1 = e;
        float sw = p[i0] + p[i1];
        d_topi[2 * t] = i0;     d_topw[2 * t]     = p[i0] / sw;
        d_topi[2 * t + 1] = i1; d_topw[2 * t + 1] = p[i1] / sw;
        atomicAdd(&d_cnt[i0], 1);
        atomicAdd(&d_cnt[i1], 1);
    }
}

__global__ void k_offsets() {
    if (threadIdx.x == 0) {
        int acc = 0;
        for (int e = 0; e < N_EXP; e++) {
            d_off[e] = acc;
            int nt = (d_cnt[e] + 127) >> 7;
            int tb = acc >> 7;
            for (int j = 0; j < nt; j++) d_tile_expert[tb + j] = e;
            acc += nt << 7;
        }
        d_ntiles = acc >> 7;
    }
}

// gather + pre-split token rows
__global__ void k_gather(const float* __restrict__ x) {
    int idx = blockIdx.x;
    int t = idx >> 1;
    __shared__ int rs;
    if (threadIdx.x == 0) {
        int e = d_topi[idx];
        int pos = atomicAdd(&d_fill[e], 1);
        int row = d_off[e] + pos;
        d_row_w[row] = d_topw[idx];
        d_row_of[idx] = row;
        rs = row;
    }
    __syncthreads();
    int row = rs;
    const float4* src = (const float4*)(x + (size_t)t * H_DIM);
    uint2* xh = (uint2*)d_xh + (size_t)row * (H_DIM / 4);
    uint2* xl = (uint2*)d_xl + (size_t)row * (H_DIM / 4);
    for (int i = threadIdx.x; i < H_DIM / 4; i += blockDim.x) {
        float4 v = src[i];
        uint32_t h0, l0, h1, l1;
        split2(v.x, v.y, h0, l0);
        split2(v.z, v.w, h1, l1);
        xh[i] = make_uint2(h0, h1);
        xl[i] = make_uint2(l0, l1);
    }
}

// ---------------- GEMM kernels ----------------------------------------------
// Per-stage SMEM layout (both GEMMs): [Ah][Al][Bh][Bl], 128 rows x 80B each.
#define ROWB   80
#define REG_SZ (128 * ROWB)       /* 10240 */
#define STG_SZ (4 * REG_SZ)       /* 40960 */
#define NST    4
#define GSMEM  (NST * STG_SZ)     /* 163840 */

// GEMM1: act(hi/lo) = split( silu(X·Wg^T) * (X·Wu^T) )
// CTA 128m x 64n; warps 4m x 2n; B region rows 0-63 = gate, 64-127 = up.
__global__ void __launch_bounds__(256, 1)
k_gemm1() {
    const int mtile = blockIdx.x;
    if (mtile >= d_ntiles) return;
    const int e  = d_tile_expert[mtile];
    const int r0 = mtile * 128;
    const int i0 = blockIdx.y * 64;

    extern __shared__ char sm[];
    const uint32_t sbase = smem_u32(sm);
    const int tid = threadIdx.x, lane = tid & 31, wid = tid >> 5;
    const int wm = (wid & 3) * 32;
    const int wn = (wid >> 2) * 32;

    // cp.async mapping: 2048 16B-chunks/stage, 8 per thread
    const char* srcp[8];
    uint32_t dsto[8];
#pragma unroll
    for (int k = 0; k < 8; k++) {
        int q = k * 256 + tid;
        int region = q >> 9, idx = q & 511, row = idx >> 2, jc = idx & 3;
        dsto[k] = region * REG_SZ + row * ROWB + jc * 16;
        size_t boff;
        const char* base;
        if (region == 0)      { base = (const char*)d_xh;  boff = ((size_t)(r0 + row) * H_DIM + jc * 8) * 2; }
        else if (region == 1) { base = (const char*)d_xl;  boff = ((size_t)(r0 + row) * H_DIM + jc * 8) * 2; }
        else {
            const char* hi = (row < 64) ? (const char*)d_wgh : (const char*)d_wuh;
            const char* lo = (row < 64) ? (const char*)d_wgl : (const char*)d_wul;
            int rr = row & 63;
            boff = ((size_t)(e * I_DIM + i0 + rr) * H_DIM + jc * 8) * 2;
            base = (region == 2) ? hi : lo;
        }
        srcp[k] = base + boff;
    }

    // ldmatrix lane geometry
    const int lj = lane >> 3, li = lane & 7;
    const uint32_t akj = (uint32_t)((lj >> 1) << 4);
    const uint32_t bkj = (uint32_t)((lj & 1) << 4);
    uint32_t faro[2], fbro[2];
#pragma unroll
    for (int m = 0; m < 2; m++) faro[m] = (uint32_t)(wm + m * 16 + li + ((lj & 1) << 3)) * ROWB + akj;
#pragma unroll
    for (int p = 0; p < 2; p++) fbro[p] = (uint32_t)(wn + p * 16 + li + ((lj >> 1) << 3)) * ROWB + bkj;

    float accg[2][4][4], accu[2][4][4];
#pragma unroll
    for (int m = 0; m < 2; m++)
#pragma unroll
        for (int n = 0; n < 4; n++)
#pragma unroll
            for (int q = 0; q < 4; q++) { accg[m][n][q] = 0.f; accu[m][n][q] = 0.f; }

#define G_ISSUE(c) do {                                                       \
    uint32_t db_ = sbase + ((c) & (NST - 1)) * STG_SZ;                        \
    size_t so_ = (size_t)(c) * 64;                                            \
    CPA(db_ + dsto[0], srcp[0] + so_); CPA(db_ + dsto[1], srcp[1] + so_);     \
    CPA(db_ + dsto[2], srcp[2] + so_); CPA(db_ + dsto[3], srcp[3] + so_);     \
    CPA(db_ + dsto[4], srcp[4] + so_); CPA(db_ + dsto[5], srcp[5] + so_);     \
    CPA(db_ + dsto[6], srcp[6] + so_); CPA(db_ + dsto[7], srcp[7] + so_);     \
    CPC();                                                                    \
} while (0)

    G_ISSUE(0); G_ISSUE(1); G_ISSUE(2);

    for (int c = 0; c < NCH1; c++) {
        int rem = NCH1 - 1 - c;
        if (rem >= 2) CPW(2); else if (rem == 1) CPW(1); else CPW(0);
        __syncthreads();
        if (c + 3 < NCH1) G_ISSUE(c + 3);

        const uint32_t sb = sbase + (c & (NST - 1)) * STG_SZ;
#pragma unroll
        for (int ks = 0; ks < 2; ks++) {
            const uint32_t kb = ks * 32;
            uint32_t ah[2][4], al[2][4];
#pragma unroll
            for (int m = 0; m < 2; m++) {
                uint32_t ad = sb + faro[m] + kb;
                LDSM4(ah[m], ad);
                LDSM4(al[m], ad + REG_SZ);
            }
            uint32_t bgh[2][4], bgl[2][4], buh[2][4], bul[2][4];
#pragma unroll
            for (int p = 0; p < 2; p++) {
                uint32_t bg = sb + 2 * REG_SZ + fbro[p] + kb;
                LDSM4(bgh[p], bg);
                LDSM4(bgl[p], bg + REG_SZ);
                LDSM4(buh[p], bg + 64 * ROWB);
                LDSM4(bul[p], bg + REG_SZ + 64 * ROWB);
            }
#pragma unroll
            for (int m = 0; m < 2; m++)
#pragma unroll
                for (int nt = 0; nt < 4; nt++) {
                    const int p = nt >> 1, q = (nt & 1) * 2;
                    mma16816(accg[m][nt], ah[m][0], ah[m][1], ah[m][2], ah[m][3], bgh[p][q], bgh[p][q + 1]);
                    mma16816(accg[m][nt], al[m][0], al[m][1], al[m][2], al[m][3], bgh[p][q], bgh[p][q + 1]);
                    mma16816(accg[m][nt], ah[m][0], ah[m][1], ah[m][2], ah[m][3], bgl[p][q], bgl[p][q + 1]);
                    mma16816(accu[m][nt], ah[m][0], ah[m][1], ah[m][2], ah[m][3], buh[p][q], buh[p][q + 1]);
                    mma16816(accu[m][nt], al[m][0], al[m][1], al[m][2], al[m][3], buh[p][q], buh[p][q + 1]);
                    mma16816(accu[m][nt], ah[m][0], ah[m][1], ah[m][2], ah[m][3], bul[p][q], bul[p][q + 1]);
                }
        }
    }

    // epilogue: silu(g)*u in fp32, re-split to bf16 hi/lo
#pragma unroll
    for (int m = 0; m < 2; m++)
#pragma unroll
        for (int nt = 0; nt < 4; nt++) {
            int row = r0 + wm + m * 16 + (lane >> 2);
            int col = i0 + wn + nt * 8 + (lane & 3) * 2;
            float a0 = silu(accg[m][nt][0]) * accu[m][nt][0];
            float a1 = silu(accg[m][nt][1]) * accu[m][nt][1];
            float a2 = silu(accg[m][nt][2]) * accu[m][nt][2];
            float a3 = silu(accg[m][nt][3]) * accu[m][nt][3];
            uint32_t h, l;
            size_t p0 = ((size_t)row * I_DIM + col) >> 1;
            split2(a0, a1, h, l);
            d_ah[p0] = h; d_al[p0] = l;
            size_t p1 = ((size_t)(row + 8) * I_DIM + col) >> 1;
            split2(a2, a3, h, l);
            d_ah[p1] = h; d_al[p1] = l;
        }
}

// GEMM2: ys = row_w * (act·Wd^T).  CTA 128m x 128n; warps 2m x 4n.
__global__ void __launch_bounds__(256, 1)
k_gemm2() {
    const int mtile = blockIdx.x;
    if (mtile >= d_ntiles) return;
    const int e  = d_tile_expert[mtile];
    const int r0 = mtile * 128;
    const int h0 = blockIdx.y * 128;

    extern __shared__ char sm[];
    const uint32_t sbase = smem_u32(sm);
    const int tid = threadIdx.x, lane = tid & 31, wid = tid >> 5;
    const int wm = (wid & 1) * 64;
    const int wn = (wid >> 1) * 32;

    const char* srcp[8];
    uint32_t dsto[8];
#pragma unroll
    for (int k = 0; k < 8; k++) {
        int q = k * 256 + tid;
        int region = q >> 9, idx = q & 511, row = idx >> 2, jc = idx & 3;
        dsto[k] = region * REG_SZ + row * ROWB + jc * 16;
        size_t boff;
        const char* base;
        if (region < 2) {
            base = (region == 0) ? (const char*)d_ah : (const char*)d_al;
            boff = ((size_t)(r0 + row) * I_DIM + jc * 8) * 2;
        } else {
            base = (region == 2) ? (const char*)d_wdh : (const char*)d_wdl;
            boff = ((size_t)(e * H_DIM + h0 + row) * I_DIM + jc * 8) * 2;
        }
        srcp[k] = base + boff;
    }

    const int lj = lane >> 3, li = lane & 7;
    const uint32_t akj = (uint32_t)((lj >> 1) << 4);
    const uint32_t bkj = (uint32_t)((lj & 1) << 4);
    uint32_t faro[4], fbro[2];
#pragma unroll
    for (int m = 0; m < 4; m++) faro[m] = (uint32_t)(wm + m * 16 + li + ((lj & 1) << 3)) * ROWB + akj;
#pragma unroll
    for (int p = 0; p < 2; p++) fbro[p] = (uint32_t)(wn + p * 16 + li + ((lj >> 1) << 3)) * ROWB + bkj;

    float acc[4][4][4];
#pragma unroll
    for (int m = 0; m < 4; m++)
#pragma unroll
        for (int n = 0; n < 4; n++)
#pragma unroll
            for (int q = 0; q < 4; q++) acc[m][n][q] = 0.f;

    G_ISSUE(0); G_ISSUE(1); G_ISSUE(2);

    for (int c = 0; c < NCH2; c++) {
        int rem = NCH2 - 1 - c;
        if (rem >= 2) CPW(2); else if (rem == 1) CPW(1); else CPW(0);
        __syncthreads();
        if (c + 3 < NCH2) G_ISSUE(c + 3);

        const uint32_t sb = sbase + (c & (NST - 1)) * STG_SZ;
#pragma unroll
        for (int ks = 0; ks < 2; ks++) {
            const uint32_t kb = ks * 32;
            uint32_t bh[2][4], bl[2][4];
#pragma unroll
            for (int p = 0; p < 2; p++) {
                uint32_t bd = sb + 2 * REG_SZ + fbro[p] + kb;
                LDSM4(bh[p], bd);
                LDSM4(bl[p], bd + REG_SZ);
            }
#pragma unroll
            for (int m = 0; m < 4; m++) {
                uint32_t ah[4], al[4];
                uint32_t ad = sb + faro[m] + kb;
                LDSM4(ah, ad);
                LDSM4(al, ad + REG_SZ);
#pragma unroll
                for (int nt = 0; nt < 4; nt++) {
                    const int p = nt >> 1, q = (nt & 1) * 2;
                    mma16816(acc[m][nt], ah[0], ah[1], ah[2], ah[3], bh[p][q], bh[p][q + 1]);
                    mma16816(acc[m][nt], al[0], al[1], al[2], al[3], bh[p][q], bh[p][q + 1]);
                    mma16816(acc[m][nt], ah[0], ah[1], ah[2], ah[3], bl[p][q], bl[p][q + 1]);
                }
            }
        }
    }

#pragma unroll
    for (int m = 0; m < 4; m++) {
        int row = r0 + wm + m * 16 + (lane >> 2);
        float w0 = d_row_w[row];
        float w1 = d_row_w[row + 8];
#pragma unroll
        for (int nt = 0; nt < 4; nt++) {
            int col = h0 + wn + nt * 8 + (lane & 3) * 2;
            float2 o0, o1;
            o0.x = acc[m][nt][0] * w0;
            o0.y = acc[m][nt][1] * w0;
            o1.x = acc[m][nt][2] * w1;
            o1.y = acc[m][nt][3] * w1;
            *(float2*)(d_ys + (size_t)row * H_DIM + col) = o0;
            *(float2*)(d_ys + (size_t)(row + 8) * H_DIM + col) = o1;
        }
    }
}

// ---------------- combine ----------------------------------------------------
__global__ void k_combine(float* __restrict__ out) {
    int t = blockIdx.x;
    int ra = d_row_of[2 * t];
    int rb = d_row_of[2 * t + 1];
    const float4* pa = (const float4*)(d_ys + (size_t)ra * H_DIM);
    const float4* pb = (const float4*)(d_ys + (size_t)rb * H_DIM);
    float4* po = (float4*)(out + (size_t)t * H_DIM);
    for (int i = threadIdx.x; i < H_DIM / 4; i += blockDim.x) {
        float4 a = pa[i], b = pb[i];
        float4 o;
        o.x = a.x + b.x; o.y = a.y + b.y; o.z = a.z + b.z; o.w = a.w + b.w;
        po[i] = o;
    }
}

// ---------------- launch -----------------------------------------------------
extern "C" void kernel_launch(void* const* d_in, const int* in_sizes, int n_in,
                              void* d_out, int out_size) {
    const float* x  = (const float*)d_in[0];
    const float* gw = (const float*)d_in[1];
    const float* wg = (const float*)d_in[2];
    const float* wu = (const float*)d_in[3];
    const float* wd = (const float*)d_in[4];
    float* out = (float*)d_out;

    cudaFuncSetAttribute(k_gemm1, cudaFuncAttributeMaxDynamicSharedMemorySize, GSMEM);
    cudaFuncSetAttribute(k_gemm2, cudaFuncAttributeMaxDynamicSharedMemorySize, GSMEM);

    uint2* wgh; cudaGetSymbolAddress((void**)&wgh, d_wgh);
    uint2* wgl; cudaGetSymbolAddress((void**)&wgl, d_wgl);
    uint2* wuh; cudaGetSymbolAddress((void**)&wuh, d_wuh);
    uint2* wul; cudaGetSymbolAddress((void**)&wul, d_wul);
    uint2* wdh; cudaGetSymbolAddress((void**)&wdh, d_wdh);
    uint2* wdl; cudaGetSymbolAddress((void**)&wdl, d_wdl);

    const int n4 = WELEM / 4;
    k_split<<<4096, 256>>>((const float4*)wg, wgh, wgl, n4);
    k_split<<<4096, 256>>>((const float4*)wu, wuh, wul, n4);
    k_split<<<4096, 256>>>((const float4*)wd, wdh, wdl, n4);

    k_init<<<1, 32>>>();
    k_router<<<T_TOK / 8, 256>>>(x, gw);
    k_offsets<<<1, 1>>>();
    k_gather<<<T_TOK * 2, 256>>>(x);

    dim3 g1(MAXT, I_DIM / 64);
    k_gemm1<<<g1, 256, GSMEM>>>();

    dim3 g2(MAXT, H_DIM / 128);
    k_gemm2<<<g2, 256, GSMEM>>>();

    k_combine<<<T_TOK, 256>>>(out);
}

// round 7
// speedup vs baseline: 1.3429x; 1.3429x over previous
#include <cuda_runtime.h>
#include <cuda_fp16.h>
#include <cstdint>

#define T_TOK 2048
#define H_DIM 2048
#define I_DIM 5632
#define N_EXP 8
#define MAXT  40
#define RMAX  (MAXT * 128)
#define NCH1  (H_DIM / 32)   /* 64  */
#define NCH2  (I_DIM / 32)   /* 176 */
#define WELEM (N_EXP * I_DIM * H_DIM)

// ---------------- scratch (device globals; allocation-free) -----------------
__device__ uint32_t d_wg16[WELEM / 2];             // fp16 weights (packed x2)
__device__ uint32_t d_wu16[WELEM / 2];
__device__ uint32_t d_wd16[WELEM / 2];
__device__ uint32_t d_xh[RMAX * H_DIM / 2], d_xl[RMAX * H_DIM / 2];   // fp16 hi/lo X
__device__ uint32_t d_ah[(size_t)RMAX * I_DIM / 2], d_al[(size_t)RMAX * I_DIM / 2];
__device__ float d_ys [RMAX * H_DIM];
__device__ int   d_topi[T_TOK * 2];
__device__ float d_topw[T_TOK * 2];
__device__ int   d_cnt [N_EXP];
__device__ int   d_fill[N_EXP];
__device__ int   d_off [N_EXP];
__device__ int   d_tile_expert[MAXT];
__device__ int   d_ntiles;
__device__ float d_row_w[RMAX];
__device__ int   d_row_of[T_TOK * 2];

// ---------------- helpers ----------------------------------------------------
__device__ __forceinline__ uint32_t smem_u32(const void* p) {
    uint32_t a;
    asm("{ .reg .u64 t; cvta.to.shared.u64 t, %1; cvt.u32.u64 %0, t; }" : "=r"(a) : "l"(p));
    return a;
}

__device__ __forceinline__ uint32_t h2u(__half2 v) {
    union { __half2 h; uint32_t u; } c; c.h = v; return c.u;
}

// fp16 hi/lo split of 2 floats
__device__ __forceinline__ void split2h(float a, float b, uint32_t& h, uint32_t& l) {
    __half2 hp = __floats2half2_rn(a, b);
    h = h2u(hp);
    float2 hf = __half22float2(hp);
    l = h2u(__floats2half2_rn(a - hf.x, b - hf.y));
}

// fp16 round-only of 2 floats
__device__ __forceinline__ uint32_t pack2h(float a, float b) {
    return h2u(__floats2half2_rn(a, b));
}

__device__ __forceinline__ void mma16816(float* c,
    uint32_t a0, uint32_t a1, uint32_t a2, uint32_t a3, uint32_t b0, uint32_t b1) {
    asm("mma.sync.aligned.m16n8k16.row.col.f32.f16.f16.f32 "
        "{%0,%1,%2,%3}, {%4,%5,%6,%7}, {%8,%9}, {%0,%1,%2,%3};"
        : "+f"(c[0]), "+f"(c[1]), "+f"(c[2]), "+f"(c[3])
        : "r"(a0), "r"(a1), "r"(a2), "r"(a3), "r"(b0), "r"(b1));
}

#define LDSM4(r, a) \
    asm volatile("ldmatrix.sync.aligned.m8n8.x4.shared.b16 {%0,%1,%2,%3}, [%4];" \
        : "=r"((r)[0]), "=r"((r)[1]), "=r"((r)[2]), "=r"((r)[3]) : "r"(a))

#define CPA(dst, src) \
    asm volatile("cp.async.cg.shared.global [%0], [%1], 16;" :: "r"(dst), "l"(src))
#define CPC() asm volatile("cp.async.commit_group;" ::: "memory")
#define CPW(n) asm volatile("cp.async.wait_group %0;" :: "n"(n) : "memory")

__device__ __forceinline__ float silu(float g) { return g / (1.f + __expf(-g)); }

// ---------------- weight fp16 round ------------------------------------------
__global__ void k_wcvt(const float4* __restrict__ src, uint2* __restrict__ dst, int n4) {
    for (int i = blockIdx.x * blockDim.x + threadIdx.x; i < n4;
         i += gridDim.x * blockDim.x) {
        float4 v = src[i];
        dst[i] = make_uint2(pack2h(v.x, v.y), pack2h(v.z, v.w));
    }
}

// ---------------- routing ----------------------------------------------------
__global__ void k_init() {
    int i = threadIdx.x;
    if (i < N_EXP) { d_cnt[i] = 0; d_fill[i] = 0; }
}

__global__ void k_router(const float* __restrict__ x, const float* __restrict__ gw) {
    int warp = threadIdx.x >> 5, lane = threadIdx.x & 31;
    int t = blockIdx.x * 8 + warp;
    const float* xr = x + (size_t)t * H_DIM;
    float acc[N_EXP];
#pragma unroll
    for (int e = 0; e < N_EXP; e++) acc[e] = 0.f;
    for (int h = lane; h < H_DIM; h += 32) {
        float xv = xr[h];
#pragma unroll
        for (int e = 0; e < N_EXP; e++) acc[e] += xv * gw[e * H_DIM + h];
    }
#pragma unroll
    for (int e = 0; e < N_EXP; e++)
#pragma unroll
        for (int o = 16; o > 0; o >>= 1) acc[e] += __shfl_xor_sync(0xffffffffu, acc[e], o);

    if (lane == 0) {
        float mx = acc[0];
#pragma unroll
        for (int e = 1; e < N_EXP; e++) mx = fmaxf(mx, acc[e]);
        float p[N_EXP], s = 0.f;
#pragma unroll
        for (int e = 0; e < N_EXP; e++) { p[e] = __expf(acc[e] - mx); s += p[e]; }
        float inv = 1.f / s;
#pragma unroll
        for (int e = 0; e < N_EXP; e++) p[e] *= inv;
        int i0 = 0;
#pragma unroll
        for (int e = 1; e < N_EXP; e++) if (p[e] > p[i0]) i0 = e;
        int i1 = (i0 == 0) ? 1 : 0;
#pragma unroll
        for (int e = 0; e < N_EXP; e++) if (e != i0 && p[e] > p[i1]) i1 = e;
        float sw = p[i0] + p[i1];
        d_topi[2 * t] = i0;     d_topw[2 * t]     = p[i0] / sw;
        d_topi[2 * t + 1] = i1; d_topw[2 * t + 1] = p[i1] / sw;
        atomicAdd(&d_cnt[i0], 1);
        atomicAdd(&d_cnt[i1], 1);
    }
}

__global__ void k_offsets() {
    if (threadIdx.x == 0) {
        int acc = 0;
        for (int e = 0; e < N_EXP; e++) {
            d_off[e] = acc;
            int nt = (d_cnt[e] + 127) >> 7;
            int tb = acc >> 7;
            for (int j = 0; j < nt; j++) d_tile_expert[tb + j] = e;
            acc += nt << 7;
        }
        d_ntiles = acc >> 7;
    }
}

// gather + fp16 hi/lo split of token rows
__global__ void k_gather(const float* __restrict__ x) {
    int idx = blockIdx.x;
    int t = idx >> 1;
    __shared__ int rs;
    if (threadIdx.x == 0) {
        int e = d_topi[idx];
        int pos = atomicAdd(&d_fill[e], 1);
        int row = d_off[e] + pos;
        d_row_w[row] = d_topw[idx];
        d_row_of[idx] = row;
        rs = row;
    }
    __syncthreads();
    int row = rs;
    const float4* src = (const float4*)(x + (size_t)t * H_DIM);
    uint2* xh = (uint2*)d_xh + (size_t)row * (H_DIM / 4);
    uint2* xl = (uint2*)d_xl + (size_t)row * (H_DIM / 4);
    for (int i = threadIdx.x; i < H_DIM / 4; i += blockDim.x) {
        float4 v = src[i];
        uint32_t h0, l0, h1, l1;
        split2h(v.x, v.y, h0, l0);
        split2h(v.z, v.w, h1, l1);
        xh[i] = make_uint2(h0, h1);
        xl[i] = make_uint2(l0, l1);
    }
}

// ---------------- GEMM kernels ----------------------------------------------
// Stage layout: 3 regions x 128 rows x 80B (64B data = k32 fp16 + 16B pad).
// GEMM1: [Ah][Al][B: rows 0-63 gate | 64-127 up]
// GEMM2: [Ah][Al][B: wd rows]
#define ROWB   80
#define REG_SZ (128 * ROWB)       /* 10240 */
#define STG_SZ (3 * REG_SZ)       /* 30720 */
#define NST    4
#define GSMEM  (NST * STG_SZ)     /* 122880 */

#define G_ISSUE(c) do {                                                       \
    uint32_t db_ = sbase + ((c) & (NST - 1)) * STG_SZ;                        \
    size_t so_ = (size_t)(c) * 64;                                            \
    CPA(db_ + dsto[0], srcp[0] + so_); CPA(db_ + dsto[1], srcp[1] + so_);     \
    CPA(db_ + dsto[2], srcp[2] + so_); CPA(db_ + dsto[3], srcp[3] + so_);     \
    CPA(db_ + dsto[4], srcp[4] + so_); CPA(db_ + dsto[5], srcp[5] + so_);     \
    CPC();                                                                    \
} while (0)

// GEMM1: act(hi/lo fp16) = split( silu(X·Wg^T) * (X·Wu^T) )
// CTA 128m x 64n; warps 4m x 2n.
__global__ void __launch_bounds__(256, 1)
k_gemm1() {
    const int mtile = blockIdx.x;
    if (mtile >= d_ntiles) return;
    const int e  = d_tile_expert[mtile];
    const int r0 = mtile * 128;
    const int i0 = blockIdx.y * 64;

    extern __shared__ char sm[];
    const uint32_t sbase = smem_u32(sm);
    const int tid = threadIdx.x, lane = tid & 31, wid = tid >> 5;
    const int wm = (wid & 3) * 32;
    const int wn = (wid >> 2) * 32;

    // cp.async: 1536 16B-chunks/stage, 6 per thread
    const char* srcp[6];
    uint32_t dsto[6];
#pragma unroll
    for (int k = 0; k < 6; k++) {
        int q = k * 256 + tid;
        int region = q >> 9, idx = q & 511, row = idx >> 2, jc = idx & 3;
        dsto[k] = region * REG_SZ + row * ROWB + jc * 16;
        const char* base;
        size_t boff;
        if (region == 0)      { base = (const char*)d_xh; boff = ((size_t)(r0 + row) * H_DIM + jc * 8) * 2; }
        else if (region == 1) { base = (const char*)d_xl; boff = ((size_t)(r0 + row) * H_DIM + jc * 8) * 2; }
        else {
            base = (row < 64) ? (const char*)d_wg16 : (const char*)d_wu16;
            int rr = row & 63;
            boff = ((size_t)(e * I_DIM + i0 + rr) * H_DIM + jc * 8) * 2;
        }
        srcp[k] = base + boff;
    }

    // ldmatrix lane geometry (16 rows x 32B fragments)
    const int lj = lane >> 3, li = lane & 7;
    const uint32_t akj = (uint32_t)((lj >> 1) << 4);
    const uint32_t bkj = (uint32_t)((lj & 1) << 4);
    uint32_t faro[2], fbro[2];
#pragma unroll
    for (int m = 0; m < 2; m++) faro[m] = (uint32_t)(wm + m * 16 + li + ((lj & 1) << 3)) * ROWB + akj;
#pragma unroll
    for (int p = 0; p < 2; p++) fbro[p] = (uint32_t)(wn + p * 16 + li + ((lj >> 1) << 3)) * ROWB + bkj;

    float accg[2][4][4], accu[2][4][4];
#pragma unroll
    for (int m = 0; m < 2; m++)
#pragma unroll
        for (int n = 0; n < 4; n++)
#pragma unroll
            for (int q = 0; q < 4; q++) { accg[m][n][q] = 0.f; accu[m][n][q] = 0.f; }

    G_ISSUE(0); G_ISSUE(1); G_ISSUE(2);

    for (int c = 0; c < NCH1; c++) {
        int rem = NCH1 - 1 - c;
        if (rem >= 2) CPW(2); else if (rem == 1) CPW(1); else CPW(0);
        __syncthreads();
        if (c + 3 < NCH1) G_ISSUE(c + 3);

        const uint32_t sb = sbase + (c & (NST - 1)) * STG_SZ;
#pragma unroll
        for (int ks = 0; ks < 2; ks++) {
            const uint32_t kb = ks * 32;
            uint32_t ah[2][4], al[2][4];
#pragma unroll
            for (int m = 0; m < 2; m++) {
                uint32_t ad = sb + faro[m] + kb;
                LDSM4(ah[m], ad);
                LDSM4(al[m], ad + REG_SZ);
            }
            uint32_t bg[2][4], bu[2][4];
#pragma unroll
            for (int p = 0; p < 2; p++) {
                uint32_t bd = sb + 2 * REG_SZ + fbro[p] + kb;
                LDSM4(bg[p], bd);
                LDSM4(bu[p], bd + 64 * ROWB);
            }
#pragma unroll
            for (int m = 0; m < 2; m++)
#pragma unroll
                for (int nt = 0; nt < 4; nt++) {
                    const int p = nt >> 1, q = (nt & 1) * 2;
                    mma16816(accg[m][nt], ah[m][0], ah[m][1], ah[m][2], ah[m][3], bg[p][q], bg[p][q + 1]);
                    mma16816(accg[m][nt], al[m][0], al[m][1], al[m][2], al[m][3], bg[p][q], bg[p][q + 1]);
                    mma16816(accu[m][nt], ah[m][0], ah[m][1], ah[m][2], ah[m][3], bu[p][q], bu[p][q + 1]);
                    mma16816(accu[m][nt], al[m][0], al[m][1], al[m][2], al[m][3], bu[p][q], bu[p][q + 1]);
                }
        }
    }

    // epilogue: silu(g)*u fp32 -> fp16 hi/lo
#pragma unroll
    for (int m = 0; m < 2; m++)
#pragma unroll
        for (int nt = 0; nt < 4; nt++) {
            int row = r0 + wm + m * 16 + (lane >> 2);
            int col = i0 + wn + nt * 8 + (lane & 3) * 2;
            float a0 = silu(accg[m][nt][0]) * accu[m][nt][0];
            float a1 = silu(accg[m][nt][1]) * accu[m][nt][1];
            float a2 = silu(accg[m][nt][2]) * accu[m][nt][2];
            float a3 = silu(accg[m][nt][3]) * accu[m][nt][3];
            uint32_t h, l;
            size_t p0 = ((size_t)row * I_DIM + col) >> 1;
            split2h(a0, a1, h, l);
            d_ah[p0] = h; d_al[p0] = l;
            size_t p1 = ((size_t)(row + 8) * I_DIM + col) >> 1;
            split2h(a2, a3, h, l);
            d_ah[p1] = h; d_al[p1] = l;
        }
}

// GEMM2: ys = row_w * (act·Wd^T).  CTA 128m x 128n; warps 2m x 4n.
__global__ void __launch_bounds__(256, 1)
k_gemm2() {
    const int mtile = blockIdx.x;
    if (mtile >= d_ntiles) return;
    const int e  = d_tile_expert[mtile];
    const int r0 = mtile * 128;
    const int h0 = blockIdx.y * 128;

    extern __shared__ char sm[];
    const uint32_t sbase = smem_u32(sm);
    const int tid = threadIdx.x, lane = tid & 31, wid = tid >> 5;
    const int wm = (wid & 1) * 64;
    const int wn = (wid >> 1) * 32;

    const char* srcp[6];
    uint32_t dsto[6];
#pragma unroll
    for (int k = 0; k < 6; k++) {
        int q = k * 256 + tid;
        int region = q >> 9, idx = q & 511, row = idx >> 2, jc = idx & 3;
        dsto[k] = region * REG_SZ + row * ROWB + jc * 16;
        const char* base;
        size_t boff;
        if (region == 0)      { base = (const char*)d_ah; boff = ((size_t)(r0 + row) * I_DIM + jc * 8) * 2; }
        else if (region == 1) { base = (const char*)d_al; boff = ((size_t)(r0 + row) * I_DIM + jc * 8) * 2; }
        else {
            base = (const char*)d_wd16;
            boff = ((size_t)(e * H_DIM + h0 + row) * I_DIM + jc * 8) * 2;
        }
        srcp[k] = base + boff;
    }

    const int lj = lane >> 3, li = lane & 7;
    const uint32_t akj = (uint32_t)((lj >> 1) << 4);
    const uint32_t bkj = (uint32_t)((lj & 1) << 4);
    uint32_t faro[4], fbro[2];
#pragma unroll
    for (int m = 0; m < 4; m++) faro[m] = (uint32_t)(wm + m * 16 + li + ((lj & 1) << 3)) * ROWB + akj;
#pragma unroll
    for (int p = 0; p < 2; p++) fbro[p] = (uint32_t)(wn + p * 16 + li + ((lj >> 1) << 3)) * ROWB + bkj;

    float acc[4][4][4];
#pragma unroll
    for (int m = 0; m < 4; m++)
#pragma unroll
        for (int n = 0; n < 4; n++)
#pragma unroll
            for (int q = 0; q < 4; q++) acc[m][n][q] = 0.f;

    G_ISSUE(0); G_ISSUE(1); G_ISSUE(2);

    for (int c = 0; c < NCH2; c++) {
        int rem = NCH2 - 1 - c;
        if (rem >= 2) CPW(2); else if (rem == 1) CPW(1); else CPW(0);
        __syncthreads();
        if (c + 3 < NCH2) G_ISSUE(c + 3);

        const uint32_t sb = sbase + (c & (NST - 1)) * STG_SZ;
#pragma unroll
        for (int ks = 0; ks < 2; ks++) {
            const uint32_t kb = ks * 32;
            uint32_t bh[2][4];
#pragma unroll
            for (int p = 0; p < 2; p++) {
                LDSM4(bh[p], sb + 2 * REG_SZ + fbro[p] + kb);
            }
#pragma unroll
            for (int m = 0; m < 4; m++) {
                uint32_t ah[4], al[4];
                uint32_t ad = sb + faro[m] + kb;
                LDSM4(ah, ad);
                LDSM4(al, ad + REG_SZ);
#pragma unroll
                for (int nt = 0; nt < 4; nt++) {
                    const int p = nt >> 1, q = (nt & 1) * 2;
                    mma16816(acc[m][nt], ah[0], ah[1], ah[2], ah[3], bh[p][q], bh[p][q + 1]);
                    mma16816(acc[m][nt], al[0], al[1], al[2], al[3], bh[p][q], bh[p][q + 1]);
                }
            }
        }
    }

#pragma unroll
    for (int m = 0; m < 4; m++) {
        int row = r0 + wm + m * 16 + (lane >> 2);
        float w0 = d_row_w[row];
        float w1 = d_row_w[row + 8];
#pragma unroll
        for (int nt = 0; nt < 4; nt++) {
            int col = h0 + wn + nt * 8 + (lane & 3) * 2;
            float2 o0, o1;
            o0.x = acc[m][nt][0] * w0;
            o0.y = acc[m][nt][1] * w0;
            o1.x = acc[m][nt][2] * w1;
            o1.y = acc[m][nt][3] * w1;
            *(float2*)(d_ys + (size_t)row * H_DIM + col) = o0;
            *(float2*)(d_ys + (size_t)(row + 8) * H_DIM + col) = o1;
        }
    }
}

// ---------------- combine ----------------------------------------------------
__global__ void k_combine(float* __restrict__ out) {
    int t = blockIdx.x;
    int ra = d_row_of[2 * t];
    int rb = d_row_of[2 * t + 1];
    const float4* pa = (const float4*)(d_ys + (size_t)ra * H_DIM);
    const float4* pb = (const float4*)(d_ys + (size_t)rb * H_DIM);
    float4* po = (float4*)(out + (size_t)t * H_DIM);
    for (int i = threadIdx.x; i < H_DIM / 4; i += blockDim.x) {
        float4 a = pa[i], b = pb[i];
        float4 o;
        o.x = a.x + b.x; o.y = a.y + b.y; o.z = a.z + b.z; o.w = a.w + b.w;
        po[i] = o;
    }
}

// ---------------- launch -----------------------------------------------------
extern "C" void kernel_launch(void* const* d_in, const int* in_sizes, int n_in,
                              void* d_out, int out_size) {
    const float* x  = (const float*)d_in[0];
    const float* gw = (const float*)d_in[1];
    const float* wg = (const float*)d_in[2];
    const float* wu = (const float*)d_in[3];
    const float* wd = (const float*)d_in[4];
    float* out = (float*)d_out;

    cudaFuncSetAttribute(k_gemm1, cudaFuncAttributeMaxDynamicSharedMemorySize, GSMEM);
    cudaFuncSetAttribute(k_gemm2, cudaFuncAttributeMaxDynamicSharedMemorySize, GSMEM);

    uint2* wg16; cudaGetSymbolAddress((void**)&wg16, d_wg16);
    uint2* wu16; cudaGetSymbolAddress((void**)&wu16, d_wu16);
    uint2* wd16; cudaGetSymbolAddress((void**)&wd16, d_wd16);

    const int n4 = WELEM / 4;
    k_wcvt<<<4096, 256>>>((const float4*)wg, wg16, n4);
    k_wcvt<<<4096, 256>>>((const float4*)wu, wu16, n4);
    k_wcvt<<<4096, 256>>>((const float4*)wd, wd16, n4);

    k_init<<<1, 32>>>();
    k_router<<<T_TOK / 8, 256>>>(x, gw);
    k_offsets<<<1, 1>>>();
    k_gather<<<T_TOK * 2, 256>>>(x);

    dim3 g1(MAXT, I_DIM / 64);
    k_gemm1<<<g1, 256, GSMEM>>>();

    dim3 g2(MAXT, H_DIM / 128);
    k_gemm2<<<g2, 256, GSMEM>>>();

    k_combine<<<T_TOK, 256>>>(out);
}

// round 8
// speedup vs baseline: 1.9482x; 1.4508x over previous
#include <cuda_runtime.h>
#include <cuda_fp16.h>
#include <cstdint>

#define T_TOK 2048
#define H_DIM 2048
#define I_DIM 5632
#define N_EXP 8
#define MAXT  40
#define RMAX  (MAXT * 128)
#define NCH1  (H_DIM / 32)   /* 64  */
#define NCH2  (I_DIM / 32)   /* 176 */
#define WELEM (N_EXP * I_DIM * H_DIM)

// ---------------- scratch (device globals; allocation-free) -----------------
__device__ uint32_t d_wg16[WELEM / 2];             // fp16 weights (packed x2)
__device__ uint32_t d_wu16[WELEM / 2];
__device__ uint32_t d_wd16[WELEM / 2];
__device__ uint32_t d_x16[RMAX * H_DIM / 2];       // fp16 gathered X
__device__ uint32_t d_a16[(size_t)RMAX * I_DIM / 2]; // fp16 act
__device__ float d_ys [RMAX * H_DIM];
__device__ int   d_topi[T_TOK * 2];
__device__ float d_topw[T_TOK * 2];
__device__ int   d_cnt [N_EXP];
__device__ int   d_fill[N_EXP];
__device__ int   d_off [N_EXP];
__device__ int   d_tile_expert[MAXT];
__device__ int   d_ntiles;
__device__ float d_row_w[RMAX];
__device__ int   d_row_of[T_TOK * 2];

// ---------------- helpers ----------------------------------------------------
__device__ __forceinline__ uint32_t smem_u32(const void* p) {
    uint32_t a;
    asm("{ .reg .u64 t; cvta.to.shared.u64 t, %1; cvt.u32.u64 %0, t; }" : "=r"(a) : "l"(p));
    return a;
}

__device__ __forceinline__ uint32_t pack2h(float a, float b) {
    union { __half2 h; uint32_t u; } c;
    c.h = __floats2half2_rn(a, b);
    return c.u;
}

__device__ __forceinline__ void mma16816(float* c,
    uint32_t a0, uint32_t a1, uint32_t a2, uint32_t a3, uint32_t b0, uint32_t b1) {
    asm("mma.sync.aligned.m16n8k16.row.col.f32.f16.f16.f32 "
        "{%0,%1,%2,%3}, {%4,%5,%6,%7}, {%8,%9}, {%0,%1,%2,%3};"
        : "+f"(c[0]), "+f"(c[1]), "+f"(c[2]), "+f"(c[3])
        : "r"(a0), "r"(a1), "r"(a2), "r"(a3), "r"(b0), "r"(b1));
}

#define LDSM4(r, a) \
    asm volatile("ldmatrix.sync.aligned.m8n8.x4.shared.b16 {%0,%1,%2,%3}, [%4];" \
        : "=r"((r)[0]), "=r"((r)[1]), "=r"((r)[2]), "=r"((r)[3]) : "r"(a))

#define CPA(dst, src) \
    asm volatile("cp.async.cg.shared.global [%0], [%1], 16;" :: "r"(dst), "l"(src))
#define CPC() asm volatile("cp.async.commit_group;" ::: "memory")
#define CPW(n) asm volatile("cp.async.wait_group %0;" :: "n"(n) : "memory")

__device__ __forceinline__ float silu(float g) { return g / (1.f + __expf(-g)); }

// ---------------- weight fp16 round ------------------------------------------
__global__ void k_wcvt(const float4* __restrict__ src, uint2* __restrict__ dst, int n4) {
    for (int i = blockIdx.x * blockDim.x + threadIdx.x; i < n4;
         i += gridDim.x * blockDim.x) {
        float4 v = src[i];
        dst[i] = make_uint2(pack2h(v.x, v.y), pack2h(v.z, v.w));
    }
}

// ---------------- routing ----------------------------------------------------
__global__ void k_init() {
    int i = threadIdx.x;
    if (i < N_EXP) { d_cnt[i] = 0; d_fill[i] = 0; }
}

__global__ void k_router(const float* __restrict__ x, const float* __restrict__ gw) {
    int warp = threadIdx.x >> 5, lane = threadIdx.x & 31;
    int t = blockIdx.x * 8 + warp;
    const float* xr = x + (size_t)t * H_DIM;
    float acc[N_EXP];
#pragma unroll
    for (int e = 0; e < N_EXP; e++) acc[e] = 0.f;
    for (int h = lane; h < H_DIM; h += 32) {
        float xv = xr[h];
#pragma unroll
        for (int e = 0; e < N_EXP; e++) acc[e] += xv * gw[e * H_DIM + h];
    }
#pragma unroll
    for (int e = 0; e < N_EXP; e++)
#pragma unroll
        for (int o = 16; o > 0; o >>= 1) acc[e] += __shfl_xor_sync(0xffffffffu, acc[e], o);

    if (lane == 0) {
        float mx = acc[0];
#pragma unroll
        for (int e = 1; e < N_EXP; e++) mx = fmaxf(mx, acc[e]);
        float p[N_EXP], s = 0.f;
#pragma unroll
        for (int e = 0; e < N_EXP; e++) { p[e] = __expf(acc[e] - mx); s += p[e]; }
        float inv = 1.f / s;
#pragma unroll
        for (int e = 0; e < N_EXP; e++) p[e] *= inv;
        int i0 = 0;
#pragma unroll
        for (int e = 1; e < N_EXP; e++) if (p[e] > p[i0]) i0 = e;
        int i1 = (i0 == 0) ? 1 : 0;
#pragma unroll
        for (int e = 0; e < N_EXP; e++) if (e != i0 && p[e] > p[i1]) i1 = e;
        float sw = p[i0] + p[i1];
        d_topi[2 * t] = i0;     d_topw[2 * t]     = p[i0] / sw;
        d_topi[2 * t + 1] = i1; d_topw[2 * t + 1] = p[i1] / sw;
        atomicAdd(&d_cnt[i0], 1);
        atomicAdd(&d_cnt[i1], 1);
    }
}

__global__ void k_offsets() {
    if (threadIdx.x == 0) {
        int acc = 0;
        for (int e = 0; e < N_EXP; e++) {
            d_off[e] = acc;
            int nt = (d_cnt[e] + 127) >> 7;
            int tb = acc >> 7;
            for (int j = 0; j < nt; j++) d_tile_expert[tb + j] = e;
            acc += nt << 7;
        }
        d_ntiles = acc >> 7;
    }
}

// gather + fp16 round of token rows
__global__ void k_gather(const float* __restrict__ x) {
    int idx = blockIdx.x;
    int t = idx >> 1;
    __shared__ int rs;
    if (threadIdx.x == 0) {
        int e = d_topi[idx];
        int pos = atomicAdd(&d_fill[e], 1);
        int row = d_off[e] + pos;
        d_row_w[row] = d_topw[idx];
        d_row_of[idx] = row;
        rs = row;
    }
    __syncthreads();
    int row = rs;
    const float4* src = (const float4*)(x + (size_t)t * H_DIM);
    uint2* xo = (uint2*)d_x16 + (size_t)row * (H_DIM / 4);
    for (int i = threadIdx.x; i < H_DIM / 4; i += blockDim.x) {
        float4 v = src[i];
        xo[i] = make_uint2(pack2h(v.x, v.y), pack2h(v.z, v.w));
    }
}

// ---------------- GEMM kernels ----------------------------------------------
// Stage layout: 2 regions x 128 rows x 80B (64B data = k32 fp16 + 16B pad).
// GEMM1: [A][B: rows 0-63 gate | 64-127 up]
// GEMM2: [A(act)][B: wd rows]
#define ROWB   80
#define REG_SZ (128 * ROWB)       /* 10240 */
#define STG_SZ (2 * REG_SZ)       /* 20480 */
#define NST    4
#define GSMEM  (NST * STG_SZ)     /* 81920 */

#define G_ISSUE(c) do {                                                       \
    uint32_t db_ = sbase + ((c) & (NST - 1)) * STG_SZ;                        \
    size_t so_ = (size_t)(c) * 64;                                            \
    CPA(db_ + dsto[0], srcp[0] + so_); CPA(db_ + dsto[1], srcp[1] + so_);     \
    CPA(db_ + dsto[2], srcp[2] + so_); CPA(db_ + dsto[3], srcp[3] + so_);     \
    CPC();                                                                    \
} while (0)

// GEMM1: act(fp16) = silu(X·Wg^T) * (X·Wu^T).  CTA 128m x 64n; warps 4m x 2n.
__global__ void __launch_bounds__(256, 1)
k_gemm1() {
    const int mtile = blockIdx.x;
    if (mtile >= d_ntiles) return;
    const int e  = d_tile_expert[mtile];
    const int r0 = mtile * 128;
    const int i0 = blockIdx.y * 64;

    extern __shared__ char sm[];
    const uint32_t sbase = smem_u32(sm);
    const int tid = threadIdx.x, lane = tid & 31, wid = tid >> 5;
    const int wm = (wid & 3) * 32;
    const int wn = (wid >> 2) * 32;

    // cp.async: 1024 16B-chunks/stage, 4 per thread
    const char* srcp[4];
    uint32_t dsto[4];
#pragma unroll
    for (int k = 0; k < 4; k++) {
        int q = k * 256 + tid;
        int region = q >> 9, idx = q & 511, row = idx >> 2, jc = idx & 3;
        dsto[k] = region * REG_SZ + row * ROWB + jc * 16;
        const char* base;
        size_t boff;
        if (region == 0) {
            base = (const char*)d_x16;
            boff = ((size_t)(r0 + row) * H_DIM + jc * 8) * 2;
        } else {
            base = (row < 64) ? (const char*)d_wg16 : (const char*)d_wu16;
            int rr = row & 63;
            boff = ((size_t)(e * I_DIM + i0 + rr) * H_DIM + jc * 8) * 2;
        }
        srcp[k] = base + boff;
    }

    // ldmatrix lane geometry
    const int lj = lane >> 3, li = lane & 7;
    const uint32_t akj = (uint32_t)((lj >> 1) << 4);
    const uint32_t bkj = (uint32_t)((lj & 1) << 4);
    uint32_t faro[2], fbro[2];
#pragma unroll
    for (int m = 0; m < 2; m++) faro[m] = (uint32_t)(wm + m * 16 + li + ((lj & 1) << 3)) * ROWB + akj;
#pragma unroll
    for (int p = 0; p < 2; p++) fbro[p] = (uint32_t)(wn + p * 16 + li + ((lj >> 1) << 3)) * ROWB + bkj;

    float accg[2][4][4], accu[2][4][4];
#pragma unroll
    for (int m = 0; m < 2; m++)
#pragma unroll
        for (int n = 0; n < 4; n++)
#pragma unroll
            for (int q = 0; q < 4; q++) { accg[m][n][q] = 0.f; accu[m][n][q] = 0.f; }

    G_ISSUE(0); G_ISSUE(1); G_ISSUE(2);

    for (int c = 0; c < NCH1; c++) {
        int rem = NCH1 - 1 - c;
        if (rem >= 2) CPW(2); else if (rem == 1) CPW(1); else CPW(0);
        __syncthreads();
        if (c + 3 < NCH1) G_ISSUE(c + 3);

        const uint32_t sb = sbase + (c & (NST - 1)) * STG_SZ;
#pragma unroll
        for (int ks = 0; ks < 2; ks++) {
            const uint32_t kb = ks * 32;
            uint32_t ah[2][4];
#pragma unroll
            for (int m = 0; m < 2; m++) LDSM4(ah[m], sb + faro[m] + kb);
            uint32_t bg[2][4], bu[2][4];
#pragma unroll
            for (int p = 0; p < 2; p++) {
                uint32_t bd = sb + REG_SZ + fbro[p] + kb;
                LDSM4(bg[p], bd);
                LDSM4(bu[p], bd + 64 * ROWB);
            }
#pragma unroll
            for (int m = 0; m < 2; m++)
#pragma unroll
                for (int nt = 0; nt < 4; nt++) {
                    const int p = nt >> 1, q = (nt & 1) * 2;
                    mma16816(accg[m][nt], ah[m][0], ah[m][1], ah[m][2], ah[m][3], bg[p][q], bg[p][q + 1]);
                    mma16816(accu[m][nt], ah[m][0], ah[m][1], ah[m][2], ah[m][3], bu[p][q], bu[p][q + 1]);
                }
        }
    }

    // epilogue: silu(g)*u fp32 -> fp16
#pragma unroll
    for (int m = 0; m < 2; m++)
#pragma unroll
        for (int nt = 0; nt < 4; nt++) {
            int row = r0 + wm + m * 16 + (lane >> 2);
            int col = i0 + wn + nt * 8 + (lane & 3) * 2;
            float a0 = silu(accg[m][nt][0]) * accu[m][nt][0];
            float a1 = silu(accg[m][nt][1]) * accu[m][nt][1];
            float a2 = silu(accg[m][nt][2]) * accu[m][nt][2];
            float a3 = silu(accg[m][nt][3]) * accu[m][nt][3];
            d_a16[((size_t)row * I_DIM + col) >> 1]       = pack2h(a0, a1);
            d_a16[((size_t)(row + 8) * I_DIM + col) >> 1] = pack2h(a2, a3);
        }
}

// GEMM2: ys = row_w * (act·Wd^T).  CTA 128m x 128n; warps 2m x 4n.
__global__ void __launch_bounds__(256, 1)
k_gemm2() {
    const int mtile = blockIdx.x;
    if (mtile >= d_ntiles) return;
    const int e  = d_tile_expert[mtile];
    const int r0 = mtile * 128;
    const int h0 = blockIdx.y * 128;

    extern __shared__ char sm[];
    const uint32_t sbase = smem_u32(sm);
    const int tid = threadIdx.x, lane = tid & 31, wid = tid >> 5;
    const int wm = (wid & 1) * 64;
    const int wn = (wid >> 1) * 32;

    const char* srcp[4];
    uint32_t dsto[4];
#pragma unroll
    for (int k = 0; k < 4; k++) {
        int q = k * 256 + tid;
        int region = q >> 9, idx = q & 511, row = idx >> 2, jc = idx & 3;
        dsto[k] = region * REG_SZ + row * ROWB + jc * 16;
        const char* base;
        size_t boff;
        if (region == 0) {
            base = (const char*)d_a16;
            boff = ((size_t)(r0 + row) * I_DIM + jc * 8) * 2;
        } else {
            base = (const char*)d_wd16;
            boff = ((size_t)(e * H_DIM + h0 + row) * I_DIM + jc * 8) * 2;
        }
        srcp[k] = base + boff;
    }

    const int lj = lane >> 3, li = lane & 7;
    const uint32_t akj = (uint32_t)((lj >> 1) << 4);
    const uint32_t bkj = (uint32_t)((lj & 1) << 4);
    uint32_t faro[4], fbro[2];
#pragma unroll
    for (int m = 0; m < 4; m++) faro[m] = (uint32_t)(wm + m * 16 + li + ((lj & 1) << 3)) * ROWB + akj;
#pragma unroll
    for (int p = 0; p < 2; p++) fbro[p] = (uint32_t)(wn + p * 16 + li + ((lj >> 1) << 3)) * ROWB + bkj;

    float acc[4][4][4];
#pragma unroll
    for (int m = 0; m < 4; m++)
#pragma unroll
        for (int n = 0; n < 4; n++)
#pragma unroll
            for (int q = 0; q < 4; q++) acc[m][n][q] = 0.f;

    G_ISSUE(0); G_ISSUE(1); G_ISSUE(2);

    for (int c = 0; c < NCH2; c++) {
        int rem = NCH2 - 1 - c;
        if (rem >= 2) CPW(2); else if (rem == 1) CPW(1); else CPW(0);
        __syncthreads();
        if (c + 3 < NCH2) G_ISSUE(c + 3);

        const uint32_t sb = sbase + (c & (NST - 1)) * STG_SZ;
#pragma unroll
        for (int ks = 0; ks < 2; ks++) {
            const uint32_t kb = ks * 32;
            uint32_t bh[2][4];
#pragma unroll
            for (int p = 0; p < 2; p++) LDSM4(bh[p], sb + REG_SZ + fbro[p] + kb);
#pragma unroll
            for (int m = 0; m < 4; m++) {
                uint32_t ah[4];
                LDSM4(ah, sb + faro[m] + kb);
#pragma unroll
                for (int nt = 0; nt < 4; nt++) {
                    const int p = nt >> 1, q = (nt & 1) * 2;
                    mma16816(acc[m][nt], ah[0], ah[1], ah[2], ah[3], bh[p][q], bh[p][q + 1]);
                }
            }
        }
    }

#pragma unroll
    for (int m = 0; m < 4; m++) {
        int row = r0 + wm + m * 16 + (lane >> 2);
        float w0 = d_row_w[row];
        float w1 = d_row_w[row + 8];
#pragma unroll
        for (int nt = 0; nt < 4; nt++) {
            int col = h0 + wn + nt * 8 + (lane & 3) * 2;
            float2 o0, o1;
            o0.x = acc[m][nt][0] * w0;
            o0.y = acc[m][nt][1] * w0;
            o1.x = acc[m][nt][2] * w1;
            o1.y = acc[m][nt][3] * w1;
            *(float2*)(d_ys + (size_t)row * H_DIM + col) = o0;
            *(float2*)(d_ys + (size_t)(row + 8) * H_DIM + col) = o1;
        }
    }
}

// ---------------- combine ----------------------------------------------------
__global__ void k_combine(float* __restrict__ out) {
    int t = blockIdx.x;
    int ra = d_row_of[2 * t];
    int rb = d_row_of[2 * t + 1];
    const float4* pa = (const float4*)(d_ys + (size_t)ra * H_DIM);
    const float4* pb = (const float4*)(d_ys + (size_t)rb * H_DIM);
    float4* po = (float4*)(out + (size_t)t * H_DIM);
    for (int i = threadIdx.x; i < H_DIM / 4; i += blockDim.x) {
        float4 a = pa[i], b = pb[i];
        float4 o;
        o.x = a.x + b.x; o.y = a.y + b.y; o.z = a.z + b.z; o.w = a.w + b.w;
        po[i] = o;
    }
}

// ---------------- launch -----------------------------------------------------
extern "C" void kernel_launch(void* const* d_in, const int* in_sizes, int n_in,
                              void* d_out, int out_size) {
    const float* x  = (const float*)d_in[0];
    const float* gw = (const float*)d_in[1];
    const float* wg = (const float*)d_in[2];
    const float* wu = (const float*)d_in[3];
    const float* wd = (const float*)d_in[4];
    float* out = (float*)d_out;

    cudaFuncSetAttribute(k_gemm1, cudaFuncAttributeMaxDynamicSharedMemorySize, GSMEM);
    cudaFuncSetAttribute(k_gemm2, cudaFuncAttributeMaxDynamicSharedMemorySize, GSMEM);

    uint2* wg16; cudaGetSymbolAddress((void**)&wg16, d_wg16);
    uint2* wu16; cudaGetSymbolAddress((void**)&wu16, d_wu16);
    uint2* wd16; cudaGetSymbolAddress((void**)&wd16, d_wd16);

    const int n4 = WELEM / 4;
    k_wcvt<<<4096, 256>>>((const float4*)wg, wg16, n4);
    k_wcvt<<<4096, 256>>>((const float4*)wu, wu16, n4);
    k_wcvt<<<4096, 256>>>((const float4*)wd, wd16, n4);

    k_init<<<1, 32>>>();
    k_router<<<T_TOK / 8, 256>>>(x, gw);
    k_offsets<<<1, 1>>>();
    k_gather<<<T_TOK * 2, 256>>>(x);

    dim3 g1(MAXT, I_DIM / 64);
    k_gemm1<<<g1, 256, GSMEM>>>();

    dim3 g2(MAXT, H_DIM / 128);
    k_gemm2<<<g2, 256, GSMEM>>>();

    k_combine<<<T_TOK, 256>>>(out);
}